// round 1
// baseline (speedup 1.0000x reference)
#include <cuda_runtime.h>
#include <cstdint>
#include <cstddef>

#define NBOX 1024
#define NCLS 151
#define NC   150
#define MROW 4096
#define KDIM 4096
#define NREL 51
#define TH   0.3f

#define OUT_PREDS (NBOX * NCLS)        // 154624
#define OUT_REL   (OUT_PREDS + NBOX)   // 155648

// ---------------- device scratch (static: no allocations allowed) ----------------
__device__ float         g_probs[NBOX * NCLS];
__device__ float4        g_sboxes[NC * NBOX];
__device__ int           g_sidx[NC * NBOX];
__device__ unsigned      g_maskbits[NC * NBOX * 32];   // 19.6 MB, L2-resident
__device__ unsigned char g_keep[NC * NBOX];

// ---------------- packed fp32x2 helpers (Blackwell full-rate fp32) ----------------
__device__ __forceinline__ unsigned long long pack2(float lo, float hi) {
    unsigned long long r;
    asm("mov.b64 %0, {%1, %2};" : "=l"(r) : "f"(lo), "f"(hi));
    return r;
}
__device__ __forceinline__ void fma2(unsigned long long& d, unsigned long long a,
                                     unsigned long long b) {
    asm("fma.rn.f32x2 %0, %1, %2, %0;" : "+l"(d) : "l"(a), "l"(b));
}
__device__ __forceinline__ void unpack2(unsigned long long v, float& lo, float& hi) {
    asm("mov.b64 {%0, %1}, %2;" : "=f"(lo), "=f"(hi) : "l"(v));
}

// ---------------- 1: softmax (warp per row) + logits passthrough ----------------
__global__ void k_softmax(const float* __restrict__ logits, float* __restrict__ out) {
    int warp = threadIdx.x >> 5, lane = threadIdx.x & 31;
    int row = blockIdx.x * 8 + warp;
    const float* rl = logits + row * NCLS;
    float v[5];
    float mx = -3.4e38f;
#pragma unroll
    for (int t = 0; t < 5; t++) {
        int c = lane + 32 * t;
        v[t] = (c < NCLS) ? rl[c] : -3.4e38f;
        mx = fmaxf(mx, v[t]);
    }
#pragma unroll
    for (int o = 16; o > 0; o >>= 1) mx = fmaxf(mx, __shfl_xor_sync(0xffffffffu, mx, o));
    float s = 0.f;
#pragma unroll
    for (int t = 0; t < 5; t++) {
        int c = lane + 32 * t;
        v[t] = (c < NCLS) ? expf(v[t] - mx) : 0.f;
        s += v[t];
    }
#pragma unroll
    for (int o = 16; o > 0; o >>= 1) s += __shfl_xor_sync(0xffffffffu, s, o);
#pragma unroll
    for (int t = 0; t < 5; t++) {
        int c = lane + 32 * t;
        if (c < NCLS) {
            g_probs[row * NCLS + c] = v[t] / s;
            out[row * NCLS + c]     = rl[c];   // obj_dists2 passthrough
        }
    }
}

// ---------------- 2: init rel_dists region with bias ----------------
__global__ void k_initrel(const float* __restrict__ b, float* __restrict__ out) {
    int i = blockIdx.x * 256 + threadIdx.x;
    if (i < MROW * NREL) out[OUT_REL + i] = b[i % NREL];
}

// ---------------- 3: GEMM  rel = vr @ W.T + b  (f32x2 packed FMA, k-split) -------
// CTA: 256 threads, tile M=512 rows, full 26 r-pairs, K-range 256 (16-way k-split).
// thread: mg = tid>>1 (4 rows), pg = tid&1 (13 r-pairs).
__global__ __launch_bounds__(256, 1) void k_gemm(const float* __restrict__ vr,
                                                 const float* __restrict__ W,
                                                 float* __restrict__ out) {
    extern __shared__ float smf[];
    float* As = smf;                                                // [512][33]
    unsigned long long* Wp = (unsigned long long*)(smf + 512 * 33); // [32][26]
    float* Wpf = (float*)Wp;

    int tid = threadIdx.x;
    int mg = tid >> 1, pg = tid & 1, pbase = pg * 13;
    int m0 = blockIdx.x * 512, k0 = blockIdx.y * 256;

    unsigned long long acc[4][13];
#pragma unroll
    for (int r = 0; r < 4; r++)
#pragma unroll
        for (int p = 0; p < 13; p++) acc[r][p] = 0ull;

    for (int kc = 0; kc < 256; kc += 32) {
        // load A tile 512x32 (coalesced float4), store padded row-major
#pragma unroll
        for (int u = 0; u < 16; u++) {
            int idx = u * 256 + tid;
            int row = idx >> 3, kq = idx & 7;
            float4 v = *(const float4*)&vr[(size_t)(m0 + row) * KDIM + (k0 + kc) + kq * 4];
            float* d = &As[row * 33 + kq * 4];
            d[0] = v.x; d[1] = v.y; d[2] = v.z; d[3] = v.w;
        }
        // load W chunk 52x32 (row 51 padded with 0), pack pairs along r
        for (int u = tid; u < 52 * 32; u += 256) {
            int r = u >> 5, kk = u & 31;
            float val = (r < NREL) ? W[r * KDIM + (k0 + kc) + kk] : 0.f;
            Wpf[kk * 52 + r] = val;
        }
        __syncthreads();

        for (int kk = 0; kk < 32; kk++) {
            float a0 = As[(mg * 4 + 0) * 33 + kk];
            float a1 = As[(mg * 4 + 1) * 33 + kk];
            float a2 = As[(mg * 4 + 2) * 33 + kk];
            float a3 = As[(mg * 4 + 3) * 33 + kk];
            unsigned long long av0 = pack2(a0, a0), av1 = pack2(a1, a1);
            unsigned long long av2 = pack2(a2, a2), av3 = pack2(a3, a3);
#pragma unroll
            for (int p = 0; p < 13; p++) {
                unsigned long long wv = Wp[kk * 26 + pbase + p];
                fma2(acc[0][p], av0, wv);
                fma2(acc[1][p], av1, wv);
                fma2(acc[2][p], av2, wv);
                fma2(acc[3][p], av3, wv);
            }
        }
        __syncthreads();
    }

#pragma unroll
    for (int r = 0; r < 4; r++) {
        int row = m0 + mg * 4 + r;
#pragma unroll
        for (int p = 0; p < 13; p++) {
            float lo, hi;
            unpack2(acc[r][p], lo, hi);
            int rc = (pbase + p) * 2;
            atomicAdd(&out[OUT_REL + row * NREL + rc], lo);
            if (rc + 1 < NREL) atomicAdd(&out[OUT_REL + row * NREL + rc + 1], hi);
        }
    }
}

// ---------------- 4: per-class descending sort (bitonic on packed u64 keys) ------
__global__ __launch_bounds__(512) void k_sort(const float4* __restrict__ boxes) {
    __shared__ unsigned long long keys[NBOX];
    int tid = threadIdx.x;
    int cls = blockIdx.x + 1;   // prob column
    for (int p = tid; p < NBOX; p += 512) {
        float sc = g_probs[p * NCLS + cls];
        // descending score, stable (ascending original index on ties)
        keys[p] = ((unsigned long long)__float_as_uint(sc) << 32) |
                  (unsigned)(0xFFFFFFFFu - (unsigned)p);
    }
    for (int k = 2; k <= NBOX; k <<= 1) {
        for (int j = k >> 1; j > 0; j >>= 1) {
            __syncthreads();
            for (int t = tid; t < NBOX; t += 512) {
                int l = t ^ j;
                if (l > t) {
                    unsigned long long a = keys[t], bb = keys[l];
                    bool desc = ((t & k) == 0);
                    if ((a < bb) == desc) { keys[t] = bb; keys[l] = a; }
                }
            }
        }
    }
    __syncthreads();
    for (int p = tid; p < NBOX; p += 512) {
        int n = (int)(0xFFFFFFFFu - (unsigned)keys[p]);
        g_sidx[(cls - 1) * NBOX + p]  = n;
        g_sboxes[(cls - 1) * NBOX + p] = boxes[n * NCLS + cls];
    }
}

// ---------------- 5: suppression bitmask matrix (upper triangle only) ------------
// block = 32 warps; warp handles one sorted row i, lane = 32-bit word w of j's.
// boxes cached in smem with bit-swapped slots -> conflict-free LDS.128.
__global__ __launch_bounds__(1024) void k_iou() {
    __shared__ float4 sb[NBOX];
    int tid = threadIdx.x;
    int cls0 = blockIdx.y;
    {
        int j = tid;
        sb[((j & 31) << 5) | (j >> 5)] = g_sboxes[cls0 * NBOX + j];
    }
    __syncthreads();
    int warpId = tid >> 5, lane = tid & 31;
    int i = blockIdx.x * 32 + warpId;
    float4 bi = sb[((i & 31) << 5) | (i >> 5)];
    float ai  = (bi.z - bi.x) * (bi.w - bi.y);
    float c3i = fmaf(TH, ai, TH * 1e-10f);
    unsigned bits = 0;
    if (lane >= ((i + 1) >> 5)) {             // word contains some j > i
        int bstart = (lane == (i >> 5)) ? ((i & 31) + 1) : 0;
        for (int b = bstart; b < 32; b++) {
            float4 bj = sb[(b << 5) | lane];  // slot of j = lane*32 + b
            float ix1 = fmaxf(bi.x, bj.x);
            float iy1 = fmaxf(bi.y, bj.y);
            float ix2 = fminf(bi.z, bj.z);
            float iy2 = fminf(bi.w, bj.w);
            float iw = fmaxf(ix2 - ix1, 0.f);
            float ih = fmaxf(iy2 - iy1, 0.f);
            float inter = iw * ih;
            float aj = (bj.z - bj.x) * (bj.w - bj.y);
            float rhs = fmaf(TH, aj, c3i);
            // inter/(ai+aj-inter+eps) > TH  <=>  inter > TH*(ai+aj+eps) - TH*inter
            if (inter > fmaf(-TH, inter, rhs)) bits |= (1u << b);
        }
    }
    g_maskbits[(cls0 * NBOX + i) * 32 + lane] = bits;   // 128B coalesced per warp
}

// ---------------- 6: greedy scan per class (warp-serial, smem-resident mask) -----
__global__ __launch_bounds__(1024) void k_scan() {
    extern __shared__ unsigned sm[];    // [32768] mask + [32] keep words
    int tid = threadIdx.x;
    int cls0 = blockIdx.x;
    const uint4* src = (const uint4*)&g_maskbits[cls0 * NBOX * 32];
    uint4* dst = (uint4*)sm;
    for (int t = tid; t < NBOX * 32 / 4; t += 1024) dst[t] = src[t];
    __syncthreads();
    if (tid < 32) {
        unsigned rem = 0, keepw = 0;    // lane l owns removed-word l
        for (int wb = 0; wb < 32; wb++) {
            unsigned alive = ~__shfl_sync(0xffffffffu, rem, wb);
            while (alive) {
                int b = __ffs(alive) - 1;
                int i = (wb << 5) + b;          // kept box (sorted pos)
                if (tid == wb) keepw |= (1u << b);
                rem |= sm[i * 32 + tid];        // suppress everything it covers
                alive &= ~__shfl_sync(0xffffffffu, rem, wb);
                alive &= ~(1u << b);
            }
        }
        sm[NBOX * 32 + tid] = keepw;
    }
    __syncthreads();
    int pos = tid;
    unsigned kept = (sm[NBOX * 32 + (pos >> 5)] >> (pos & 31)) & 1u;
    int n = g_sidx[cls0 * NBOX + pos];
    g_keep[cls0 * NBOX + n] = (unsigned char)kept;
}

// ---------------- 7: masked argmax -> obj_preds ----------------
__global__ void k_argmax(float* __restrict__ out) {
    int n = blockIdx.x * 256 + threadIdx.x;
    if (n >= NBOX) return;
    float best = -1.f;
    int bestc = 0;
    for (int c = 1; c < NCLS; c++) {
        float v = g_keep[(c - 1) * NBOX + n] ? g_probs[n * NCLS + c] : 0.f;
        if (v > best) { best = v; bestc = c; }   // strict > == first occurrence
    }
    out[OUT_PREDS + n] = (float)bestc;           // argmax over [1:] + 1 == c
}

// ---------------- launch ----------------
extern "C" void kernel_launch(void* const* d_in, const int* in_sizes, int n_in,
                              void* d_out, int out_size) {
    const float*  logits = (const float*)d_in[0];
    const float*  vr     = (const float*)d_in[1];
    const float4* boxes  = (const float4*)d_in[2];
    const float*  W      = (const float*)d_in[3];
    const float*  b      = (const float*)d_in[4];
    float* out = (float*)d_out;

    const int scan_smem = NBOX * 32 * 4 + 128;           // 131200
    const int gemm_smem = 512 * 33 * 4 + 32 * 26 * 8;    // 74240
    cudaFuncSetAttribute(k_scan, cudaFuncAttributeMaxDynamicSharedMemorySize, scan_smem);
    cudaFuncSetAttribute(k_gemm, cudaFuncAttributeMaxDynamicSharedMemorySize, gemm_smem);

    k_softmax<<<128, 256>>>(logits, out);
    k_initrel<<<(MROW * NREL + 255) / 256, 256>>>(b, out);
    k_gemm<<<dim3(8, 16), 256, gemm_smem>>>(vr, W, out);
    k_sort<<<NC, 512>>>(boxes);
    k_iou<<<dim3(32, NC), 1024>>>();
    k_scan<<<NC, 1024, scan_smem>>>();
    k_argmax<<<4, 256>>>(out);
}

// round 2
// speedup vs baseline: 1.0999x; 1.0999x over previous
#include <cuda_runtime.h>
#include <cstdint>
#include <cstddef>

#define NBOX 1024
#define NCLS 151
#define NC   150
#define MROW 4096
#define KDIM 4096
#define NREL 51
#define TH   0.3f

#define OUT_PREDS (NBOX * NCLS)        // 154624
#define OUT_REL   (OUT_PREDS + NBOX)   // 155648
#define NCELL 16896                    // triangle cells per class

// ---------------- device scratch (static: no allocations allowed) ----------------
__device__ float         g_probs[NBOX * NCLS];
__device__ float4        g_sboxes[NC * NBOX];
__device__ int           g_sidx[NC * NBOX];
__device__ unsigned      g_maskbits[NC * NBOX * 32];   // zero-init; lower-tri words stay 0
__device__ unsigned char g_keep[NC * NBOX];

// ---------------- packed fp32x2 helpers ----------------
__device__ __forceinline__ unsigned long long pack2(float lo, float hi) {
    unsigned long long r;
    asm("mov.b64 %0, {%1, %2};" : "=l"(r) : "f"(lo), "f"(hi));
    return r;
}
__device__ __forceinline__ void fma2(unsigned long long& d, unsigned long long a,
                                     unsigned long long b) {
    asm("fma.rn.f32x2 %0, %1, %2, %0;" : "+l"(d) : "l"(a), "l"(b));
}
__device__ __forceinline__ void unpack2(unsigned long long v, float& lo, float& hi) {
    asm("mov.b64 {%0, %1}, %2;" : "=f"(lo), "=f"(hi) : "l"(v));
}

// ---------------- 1: softmax (warp per row) + logits passthrough ----------------
__global__ void k_softmax(const float* __restrict__ logits, float* __restrict__ out) {
    int warp = threadIdx.x >> 5, lane = threadIdx.x & 31;
    int row = blockIdx.x * 8 + warp;
    const float* rl = logits + row * NCLS;
    float v[5];
    float mx = -3.4e38f;
#pragma unroll
    for (int t = 0; t < 5; t++) {
        int c = lane + 32 * t;
        v[t] = (c < NCLS) ? rl[c] : -3.4e38f;
        mx = fmaxf(mx, v[t]);
    }
#pragma unroll
    for (int o = 16; o > 0; o >>= 1) mx = fmaxf(mx, __shfl_xor_sync(0xffffffffu, mx, o));
    float s = 0.f;
#pragma unroll
    for (int t = 0; t < 5; t++) {
        int c = lane + 32 * t;
        v[t] = (c < NCLS) ? expf(v[t] - mx) : 0.f;
        s += v[t];
    }
#pragma unroll
    for (int o = 16; o > 0; o >>= 1) s += __shfl_xor_sync(0xffffffffu, s, o);
#pragma unroll
    for (int t = 0; t < 5; t++) {
        int c = lane + 32 * t;
        if (c < NCLS) {
            g_probs[row * NCLS + c] = v[t] / s;
            out[row * NCLS + c]     = rl[c];
        }
    }
}

// ---------------- 2: init rel_dists region with bias ----------------
__global__ void k_initrel(const float* __restrict__ b, float* __restrict__ out) {
    int i = blockIdx.x * 256 + threadIdx.x;
    if (i < MROW * NREL) out[OUT_REL + i] = b[i % NREL];
}

// ---------------- 3: GEMM  rel = vr @ W.T + b  (f32x2 packed FMA, k-split) -------
__global__ __launch_bounds__(256, 1) void k_gemm(const float* __restrict__ vr,
                                                 const float* __restrict__ W,
                                                 float* __restrict__ out) {
    extern __shared__ float smf[];
    float* As = smf;                                                // [512][33]
    unsigned long long* Wp = (unsigned long long*)(smf + 512 * 33); // [32][26]
    float* Wpf = (float*)Wp;

    int tid = threadIdx.x;
    int mg = tid >> 1, pg = tid & 1, pbase = pg * 13;
    int m0 = blockIdx.x * 512, k0 = blockIdx.y * 256;

    unsigned long long acc[4][13];
#pragma unroll
    for (int r = 0; r < 4; r++)
#pragma unroll
        for (int p = 0; p < 13; p++) acc[r][p] = 0ull;

    for (int kc = 0; kc < 256; kc += 32) {
#pragma unroll
        for (int u = 0; u < 16; u++) {
            int idx = u * 256 + tid;
            int row = idx >> 3, kq = idx & 7;
            float4 v = *(const float4*)&vr[(size_t)(m0 + row) * KDIM + (k0 + kc) + kq * 4];
            float* d = &As[row * 33 + kq * 4];
            d[0] = v.x; d[1] = v.y; d[2] = v.z; d[3] = v.w;
        }
        for (int u = tid; u < 52 * 32; u += 256) {
            int r = u >> 5, kk = u & 31;
            float val = (r < NREL) ? W[r * KDIM + (k0 + kc) + kk] : 0.f;
            Wpf[kk * 52 + r] = val;
        }
        __syncthreads();

        for (int kk = 0; kk < 32; kk++) {
            float a0 = As[(mg * 4 + 0) * 33 + kk];
            float a1 = As[(mg * 4 + 1) * 33 + kk];
            float a2 = As[(mg * 4 + 2) * 33 + kk];
            float a3 = As[(mg * 4 + 3) * 33 + kk];
            unsigned long long av0 = pack2(a0, a0), av1 = pack2(a1, a1);
            unsigned long long av2 = pack2(a2, a2), av3 = pack2(a3, a3);
#pragma unroll
            for (int p = 0; p < 13; p++) {
                unsigned long long wv = Wp[kk * 26 + pbase + p];
                fma2(acc[0][p], av0, wv);
                fma2(acc[1][p], av1, wv);
                fma2(acc[2][p], av2, wv);
                fma2(acc[3][p], av3, wv);
            }
        }
        __syncthreads();
    }

#pragma unroll
    for (int r = 0; r < 4; r++) {
        int row = m0 + mg * 4 + r;
#pragma unroll
        for (int p = 0; p < 13; p++) {
            float lo, hi;
            unpack2(acc[r][p], lo, hi);
            int rc = (pbase + p) * 2;
            atomicAdd(&out[OUT_REL + row * NREL + rc], lo);
            if (rc + 1 < NREL) atomicAdd(&out[OUT_REL + row * NREL + rc + 1], hi);
        }
    }
}

// ---------------- 4: per-class descending sort (register/shfl bitonic) -----------
// 512 threads, thread t holds elements 2t, 2t+1. j<=32 passes via shfl/in-thread,
// only j>=64 passes through smem (10 smem passes instead of 55 barrier passes).
__global__ __launch_bounds__(512) void k_sort(const float4* __restrict__ boxes) {
    __shared__ unsigned long long keys[NBOX];
    int t = threadIdx.x;
    int cls = blockIdx.x + 1;

    auto mkkey = [&](int p) {
        float sc = g_probs[p * NCLS + cls];
        return ((unsigned long long)__float_as_uint(sc) << 32) |
               (unsigned)(0xFFFFFFFFu - (unsigned)p);
    };
    unsigned long long v0 = mkkey(2 * t), v1 = mkkey(2 * t + 1);

    for (int k = 2; k <= NBOX; k <<= 1) {
        for (int j = k >> 1; j >= 1; j >>= 1) {
            if (j >= 64) {
                __syncthreads();
                keys[2 * t] = v0; keys[2 * t + 1] = v1;
                __syncthreads();
                unsigned long long u0 = keys[(2 * t) ^ j];
                unsigned long long u1 = keys[((2 * t) ^ j) + 1];
                bool takeMax = (((t & (j >> 1)) == 0) == ((t & (k >> 1)) == 0));
                v0 = takeMax ? (v0 > u0 ? v0 : u0) : (v0 < u0 ? v0 : u0);
                v1 = takeMax ? (v1 > u1 ? v1 : u1) : (v1 < u1 ? v1 : u1);
            } else if (j >= 2) {
                unsigned long long u0 = __shfl_xor_sync(0xffffffffu, v0, j >> 1);
                unsigned long long u1 = __shfl_xor_sync(0xffffffffu, v1, j >> 1);
                bool takeMax = (((t & (j >> 1)) == 0) == ((t & (k >> 1)) == 0));
                v0 = takeMax ? (v0 > u0 ? v0 : u0) : (v0 < u0 ? v0 : u0);
                v1 = takeMax ? (v1 > u1 ? v1 : u1) : (v1 < u1 ? v1 : u1);
            } else {
                bool desc = ((t & (k >> 1)) == 0);
                unsigned long long hi = v0 > v1 ? v0 : v1;
                unsigned long long lo = v0 > v1 ? v1 : v0;
                v0 = desc ? hi : lo;
                v1 = desc ? lo : hi;
            }
        }
    }
    int n0 = (int)(0xFFFFFFFFu - (unsigned)v0);
    int n1 = (int)(0xFFFFFFFFu - (unsigned)v1);
    g_sidx[(cls - 1) * NBOX + 2 * t]     = n0;
    g_sidx[(cls - 1) * NBOX + 2 * t + 1] = n1;
    g_sboxes[(cls - 1) * NBOX + 2 * t]     = boxes[n0 * NCLS + cls];
    g_sboxes[(cls - 1) * NBOX + 2 * t + 1] = boxes[n1 * NCLS + cls];
}

// ---------------- 5: suppression bitmask, TRUE triangle only ---------------------
// Flattened valid cells (row, word>=row/32): 16896 per class. Each lane owns one
// cell, found by inverting cum(r) = 32r - 16q(q-1) - s*q (q=r>>5, s=r&31).
__global__ __launch_bounds__(1024) void k_iou() {
    __shared__ float4 sb[NBOX];
    __shared__ float  ta[NBOX];
    int tid = threadIdx.x, cls = blockIdx.y;
    {
        float4 b4 = g_sboxes[cls * NBOX + tid];
        int slot = ((tid & 31) << 5) | (tid >> 5);
        sb[slot] = b4;
        ta[slot] = TH * ((b4.z - b4.x) * (b4.w - b4.y));
    }
    __syncthreads();

    int c = blockIdx.x * 1024 + tid;
    if (c >= NCELL) return;

    int lo = 0, hi = 1023;
    while (lo < hi) {
        int mid = (lo + hi + 1) >> 1;
        int q = mid >> 5, s = mid & 31;
        int cm = 32 * mid - 16 * q * (q - 1) - s * q;
        if (cm <= c) lo = mid; else hi = mid - 1;
    }
    int row = lo;
    int q = row >> 5, s = row & 31;
    int cm = 32 * row - 16 * q * (q - 1) - s * q;
    int word = q + (c - cm);

    float4 bi = sb[((row & 31) << 5) | (row >> 5)];
    float ai  = (bi.z - bi.x) * (bi.w - bi.y);
    float c3  = fmaf(TH, ai, TH * 1e-10f);
    unsigned bits = 0;
#pragma unroll 8
    for (int b = 0; b < 32; b++) {
        int slot = (b << 5) | word;
        float4 bj = sb[slot];
        float rhs = ta[slot] + c3;
        float ix1 = fmaxf(bi.x, bj.x);
        float iy1 = fmaxf(bi.y, bj.y);
        float ix2 = fminf(bi.z, bj.z);
        float iy2 = fminf(bi.w, bj.w);
        float iw = fmaxf(ix2 - ix1, 0.f);
        float ih = fmaxf(iy2 - iy1, 0.f);
        float inter = iw * ih;
        if (fmaf(TH, inter, inter) > rhs) bits |= (1u << b);
    }
    if (word == q) bits &= (0xFFFFFFFEu << s);   // only j > row in diagonal word
    g_maskbits[(cls * NBOX + row) * 32 + word] = bits;
}

// ---------------- 6: greedy scan, two-level (reg-shfl in-word, batched LDS OR) ---
__global__ __launch_bounds__(1024) void k_scan() {
    extern __shared__ unsigned sm[];   // 32768 swizzled words + 32 keep words
    int tid = threadIdx.x, cls = blockIdx.x;
    const unsigned* src = g_maskbits + (size_t)cls * NBOX * 32;
    for (int t = tid; t < NBOX * 32; t += 1024) {
        int row = t >> 5, w = t & 31;
        sm[(row << 5) | (w ^ (row & 31))] = src[t];   // XOR swizzle: diag gather CF
    }
    __syncthreads();

    if (tid < 32) {
        int l = tid;
        unsigned rem = 0, keepw = 0;               // lane l owns suppressed-word l
        for (int wb = 0; wb < 32; wb++) {
            // diag word of row (wb*32 + l): in-word suppression bits (j > row)
            unsigned diag = sm[(((wb << 5) | l) << 5) | (wb ^ l)];
            unsigned alive = ~__shfl_sync(0xffffffffu, rem, wb);
            unsigned K = 0;
            while (alive) {                         // warp-uniform
                int b = __ffs(alive) - 1;
                K |= (1u << b);
                unsigned supp = __shfl_sync(0xffffffffu, diag, b);
                alive &= ~supp;
                alive &= ~(1u << b);
            }
            if (l == wb) keepw = K;
            unsigned kk = K;                        // batch-OR kept rows (parallel LDS)
            while (kk) {
                int b = __ffs(kk) - 1; kk &= kk - 1;
                int R = (wb << 5) | b;
                rem |= sm[(R << 5) | (l ^ (R & 31))];
            }
        }
        sm[NBOX * 32 + l] = keepw;
    }
    __syncthreads();
    unsigned kept = (sm[NBOX * 32 + (tid >> 5)] >> (tid & 31)) & 1u;
    int n = g_sidx[cls * NBOX + tid];
    g_keep[cls * NBOX + n] = (unsigned char)kept;
}

// ---------------- 7: masked argmax -> obj_preds ----------------
__global__ void k_argmax(float* __restrict__ out) {
    int n = blockIdx.x * 256 + threadIdx.x;
    if (n >= NBOX) return;
    float best = -1.f;
    int bestc = 0;
    for (int c = 1; c < NCLS; c++) {
        float v = g_keep[(c - 1) * NBOX + n] ? g_probs[n * NCLS + c] : 0.f;
        if (v > best) { best = v; bestc = c; }
    }
    out[OUT_PREDS + n] = (float)bestc;
}

// ---------------- launch (GEMM branch forked onto a second captured stream) ------
extern "C" void kernel_launch(void* const* d_in, const int* in_sizes, int n_in,
                              void* d_out, int out_size) {
    const float*  logits = (const float*)d_in[0];
    const float*  vr     = (const float*)d_in[1];
    const float4* boxes  = (const float4*)d_in[2];
    const float*  W      = (const float*)d_in[3];
    const float*  b      = (const float*)d_in[4];
    float* out = (float*)d_out;

    static cudaStream_t s2 = nullptr;
    static cudaEvent_t  evA = nullptr, evB = nullptr;
    if (!s2) {
        cudaStreamCreateWithFlags(&s2, cudaStreamNonBlocking);
        cudaEventCreateWithFlags(&evA, cudaEventDisableTiming);
        cudaEventCreateWithFlags(&evB, cudaEventDisableTiming);
    }

    const int scan_smem = (NBOX * 32 + 32) * 4;          // 131200
    const int gemm_smem = 512 * 33 * 4 + 32 * 26 * 8;    // 74240
    cudaFuncSetAttribute(k_scan, cudaFuncAttributeMaxDynamicSharedMemorySize, scan_smem);
    cudaFuncSetAttribute(k_gemm, cudaFuncAttributeMaxDynamicSharedMemorySize, gemm_smem);

    // fork GEMM branch
    cudaEventRecord(evA, 0);
    cudaStreamWaitEvent(s2, evA, 0);
    k_initrel<<<(MROW * NREL + 255) / 256, 256, 0, s2>>>(b, out);
    k_gemm<<<dim3(8, 16), 256, gemm_smem, s2>>>(vr, W, out);
    cudaEventRecord(evB, s2);

    // NMS chain on capture stream
    k_softmax<<<128, 256>>>(logits, out);
    k_sort<<<NC, 512>>>(boxes);
    k_iou<<<dim3((NCELL + 1023) / 1024, NC), 1024>>>();
    k_scan<<<NC, 1024, scan_smem>>>();
    k_argmax<<<4, 256>>>(out);

    // join
    cudaStreamWaitEvent(0, evB, 0);
}

// round 4
// speedup vs baseline: 1.3635x; 1.2397x over previous
#include <cuda_runtime.h>
#include <cstdint>
#include <cstddef>

#define NBOX 1024
#define NCLS 151
#define NC   150
#define MROW 4096
#define KDIM 4096
#define NREL 51
#define TH   0.3f

#define OUT_PREDS (NBOX * NCLS)        // 154624
#define OUT_REL   (OUT_PREDS + NBOX)   // 155648
#define NTASK 528                      // triangle (g,w) tiles per class

// ---------------- device scratch ----------------
__device__ float         g_probs[NBOX * NCLS];
__device__ float4        g_sboxes[NC * NBOX];
__device__ int           g_sidx[NC * NBOX];
__device__ unsigned      g_maskbits[NC * NBOX * 32];   // zero-init; lower-tri stays 0
__device__ unsigned char g_keep[NBOX * NC];            // [box][cls]

// ---------------- packed fp32x2 helpers ----------------
__device__ __forceinline__ unsigned long long pack2(float lo, float hi) {
    unsigned long long r;
    asm("mov.b64 %0, {%1, %2};" : "=l"(r) : "f"(lo), "f"(hi));
    return r;
}
__device__ __forceinline__ void fma2(unsigned long long& d, unsigned long long a,
                                     unsigned long long b) {
    asm("fma.rn.f32x2 %0, %1, %2, %0;" : "+l"(d) : "l"(a), "l"(b));
}
__device__ __forceinline__ void unpack2(unsigned long long v, float& lo, float& hi) {
    asm("mov.b64 {%0, %1}, %2;" : "=f"(lo), "=f"(hi) : "l"(v));
}

// ---------------- 1: softmax (warp per row) + logits passthrough ----------------
__global__ void k_softmax(const float* __restrict__ logits, float* __restrict__ out) {
    int warp = threadIdx.x >> 5, lane = threadIdx.x & 31;
    int row = blockIdx.x * 8 + warp;
    const float* rl = logits + row * NCLS;
    float v[5];
    float mx = -3.4e38f;
#pragma unroll
    for (int t = 0; t < 5; t++) {
        int c = lane + 32 * t;
        v[t] = (c < NCLS) ? rl[c] : -3.4e38f;
        mx = fmaxf(mx, v[t]);
    }
#pragma unroll
    for (int o = 16; o > 0; o >>= 1) mx = fmaxf(mx, __shfl_xor_sync(0xffffffffu, mx, o));
    float s = 0.f;
#pragma unroll
    for (int t = 0; t < 5; t++) {
        int c = lane + 32 * t;
        v[t] = (c < NCLS) ? expf(v[t] - mx) : 0.f;
        s += v[t];
    }
#pragma unroll
    for (int o = 16; o > 0; o >>= 1) s += __shfl_xor_sync(0xffffffffu, s, o);
#pragma unroll
    for (int t = 0; t < 5; t++) {
        int c = lane + 32 * t;
        if (c < NCLS) {
            g_probs[row * NCLS + c] = v[t] / s;
            out[row * NCLS + c]     = rl[c];
        }
    }
}

// ---------------- 2: init rel_dists region with bias ----------------
__global__ void k_initrel(const float* __restrict__ b, float* __restrict__ out) {
    int i = blockIdx.x * 256 + threadIdx.x;
    if (i < MROW * NREL) out[OUT_REL + i] = b[i % NREL];
}

// ---------------- 3: GEMM  rel = vr @ W.T + b  (f32x2, M-tile 256, 16-way ksplit)
__global__ __launch_bounds__(256) void k_gemm(const float* __restrict__ vr,
                                              const float* __restrict__ W,
                                              float* __restrict__ out) {
    extern __shared__ float smf[];
    float* As = smf;                                                // [256][33]
    unsigned long long* Wp = (unsigned long long*)(smf + 256 * 33); // [32][26]
    float* Wpf = (float*)Wp;

    int tid = threadIdx.x;
    int mg = tid >> 1, pg = tid & 1, pbase = pg * 13;
    int m0 = blockIdx.x * 256, k0 = blockIdx.y * 256;

    unsigned long long acc[2][13];
#pragma unroll
    for (int r = 0; r < 2; r++)
#pragma unroll
        for (int p = 0; p < 13; p++) acc[r][p] = 0ull;

    for (int kc = 0; kc < 256; kc += 32) {
#pragma unroll
        for (int u = 0; u < 8; u++) {
            int idx = u * 256 + tid;
            int row = idx >> 3, kq = idx & 7;
            float4 v = *(const float4*)&vr[(size_t)(m0 + row) * KDIM + (k0 + kc) + kq * 4];
            float* d = &As[row * 33 + kq * 4];
            d[0] = v.x; d[1] = v.y; d[2] = v.z; d[3] = v.w;
        }
        for (int u = tid; u < 52 * 32; u += 256) {
            int r = u >> 5, kk = u & 31;
            float val = (r < NREL) ? W[r * KDIM + (k0 + kc) + kk] : 0.f;
            Wpf[kk * 52 + r] = val;
        }
        __syncthreads();

        for (int kk = 0; kk < 32; kk++) {
            float a0 = As[(mg * 2 + 0) * 33 + kk];
            float a1 = As[(mg * 2 + 1) * 33 + kk];
            unsigned long long av0 = pack2(a0, a0), av1 = pack2(a1, a1);
#pragma unroll
            for (int p = 0; p < 13; p++) {
                unsigned long long wv = Wp[kk * 26 + pbase + p];
                fma2(acc[0][p], av0, wv);
                fma2(acc[1][p], av1, wv);
            }
        }
        __syncthreads();
    }

#pragma unroll
    for (int r = 0; r < 2; r++) {
        int row = m0 + mg * 2 + r;
#pragma unroll
        for (int p = 0; p < 13; p++) {
            float lo, hi;
            unpack2(acc[r][p], lo, hi);
            int rc = (pbase + p) * 2;
            atomicAdd(&out[OUT_REL + row * NREL + rc], lo);
            if (rc + 1 < NREL) atomicAdd(&out[OUT_REL + row * NREL + rc + 1], hi);
        }
    }
}

// ---------------- 4: per-class descending sort (register/shfl bitonic) -----------
__global__ __launch_bounds__(512) void k_sort(const float4* __restrict__ boxes) {
    __shared__ unsigned long long keys[NBOX];
    int t = threadIdx.x;
    int cls = blockIdx.x + 1;

    auto mkkey = [&](int p) {
        float sc = g_probs[p * NCLS + cls];
        return ((unsigned long long)__float_as_uint(sc) << 32) |
               (unsigned)(0xFFFFFFFFu - (unsigned)p);
    };
    unsigned long long v0 = mkkey(2 * t), v1 = mkkey(2 * t + 1);

    for (int k = 2; k <= NBOX; k <<= 1) {
        for (int j = k >> 1; j >= 1; j >>= 1) {
            if (j >= 64) {
                __syncthreads();
                keys[2 * t] = v0; keys[2 * t + 1] = v1;
                __syncthreads();
                unsigned long long u0 = keys[(2 * t) ^ j];
                unsigned long long u1 = keys[((2 * t) ^ j) + 1];
                bool takeMax = (((t & (j >> 1)) == 0) == ((t & (k >> 1)) == 0));
                v0 = takeMax ? (v0 > u0 ? v0 : u0) : (v0 < u0 ? v0 : u0);
                v1 = takeMax ? (v1 > u1 ? v1 : u1) : (v1 < u1 ? v1 : u1);
            } else if (j >= 2) {
                unsigned long long u0 = __shfl_xor_sync(0xffffffffu, v0, j >> 1);
                unsigned long long u1 = __shfl_xor_sync(0xffffffffu, v1, j >> 1);
                bool takeMax = (((t & (j >> 1)) == 0) == ((t & (k >> 1)) == 0));
                v0 = takeMax ? (v0 > u0 ? v0 : u0) : (v0 < u0 ? v0 : u0);
                v1 = takeMax ? (v1 > u1 ? v1 : u1) : (v1 < u1 ? v1 : u1);
            } else {
                bool desc = ((t & (k >> 1)) == 0);
                unsigned long long hi = v0 > v1 ? v0 : v1;
                unsigned long long lo = v0 > v1 ? v1 : v0;
                v0 = desc ? hi : lo;
                v1 = desc ? lo : hi;
            }
        }
    }
    int n0 = (int)(0xFFFFFFFFu - (unsigned)v0);
    int n1 = (int)(0xFFFFFFFFu - (unsigned)v1);
    g_sidx[(cls - 1) * NBOX + 2 * t]     = n0;
    g_sidx[(cls - 1) * NBOX + 2 * t + 1] = n1;
    g_sboxes[(cls - 1) * NBOX + 2 * t]     = boxes[n0 * NCLS + cls];
    g_sboxes[(cls - 1) * NBOX + 2 * t + 1] = boxes[n1 * NCLS + cls];
}

// ---------------- 5: suppression bitmask: warp = (row-group g, word w), w>=g -----
// lane = row in group (bi in registers); bj is warp-uniform -> broadcast LDS.
__global__ __launch_bounds__(1024) void k_iou() {
    __shared__ float4 sb[NBOX];
    __shared__ float  ta[NBOX];
    int tid = threadIdx.x, cls = blockIdx.y;
    {
        float4 b4 = g_sboxes[cls * NBOX + tid];
        sb[tid] = b4;
        ta[tid] = TH * ((b4.z - b4.x) * (b4.w - b4.y));
    }
    __syncthreads();
    int task = blockIdx.x * 32 + (tid >> 5);
    if (task >= NTASK) return;

    // invert base(g) = 32g - g(g-1)/2
    int g = (int)((65.0f - sqrtf(4225.0f - 8.0f * (float)task)) * 0.5f);
    while (32 * (g + 1) - (((g + 1) * g) >> 1) <= task) g++;
    while (32 * g - ((g * (g - 1)) >> 1) > task) g--;
    int w = g + (task - (32 * g - ((g * (g - 1)) >> 1)));

    int lane = tid & 31;
    int r = (g << 5) | lane;
    float4 bi = sb[r];
    float c3i = ta[r] + TH * 1e-10f;
    int jbase = w << 5;
    unsigned bits = 0;
#pragma unroll 8
    for (int b = 0; b < 32; b++) {
        float4 bj = sb[jbase + b];                 // broadcast (warp-uniform)
        float rhs = c3i + ta[jbase + b];
        float ix1 = fmaxf(bi.x, bj.x);
        float iy1 = fmaxf(bi.y, bj.y);
        float ix2 = fminf(bi.z, bj.z);
        float iy2 = fminf(bi.w, bj.w);
        float iw = fmaxf(ix2 - ix1, 0.f);
        float ih = fmaxf(iy2 - iy1, 0.f);
        float inter = iw * ih;
        // inter/(ai+aj-inter+eps) > TH  <=>  inter + TH*inter > TH*(ai+aj+eps)
        if (fmaf(TH, inter, inter) > rhs) bits |= (1u << b);
    }
    if (w == g) bits &= (0xFFFFFFFEu << lane);     // only j > row in diagonal word
    g_maskbits[(cls * NBOX + r) * 32 + w] = bits;
}

// ---------------- 6: greedy scan: register-resolve per word, batched OR ----------
__global__ __launch_bounds__(512) void k_scan() {
    extern __shared__ unsigned sm[];   // [1024][32] natural + 32 keep words
    int tid = threadIdx.x, cls = blockIdx.x;
    const uint4* src = (const uint4*)(g_maskbits + (size_t)cls * NBOX * 32);
    uint4* dst = (uint4*)sm;
    for (int t = tid; t < NBOX * 8; t += 512) dst[t] = src[t];
    __syncthreads();

    if (tid < 32) {
        int l = tid;
        unsigned rem = 0;                          // lane l owns suppressed-word l
        for (int wb = 0; wb < 32; wb++) {
            unsigned diag[32];                     // broadcast prefetch (overlapped)
#pragma unroll
            for (int b = 0; b < 32; b++) diag[b] = sm[((((wb << 5) | b) << 5)) | wb];
            unsigned alive = ~__shfl_sync(0xffffffffu, rem, wb);
            unsigned K = 0;
#pragma unroll
            for (int b = 0; b < 32; b++) {         // branchless greedy, regs only
                unsigned m = (unsigned)(-(int)((alive >> b) & 1u));
                K |= (1u << b) & m;
                alive &= ~(diag[b] & m);
            }
            if (l == 0) sm[NBOX * 32 + wb] = K;    // K identical on all lanes
            unsigned kk = K;                       // batch-OR kept rows (CF, pipelined)
            while (kk) {
                int b = __ffs(kk) - 1; kk &= kk - 1;
                rem |= sm[((((wb << 5) | b) << 5)) | l];
            }
        }
    }
    __syncthreads();
    for (int p = tid; p < NBOX; p += 512) {
        unsigned kept = (sm[NBOX * 32 + (p >> 5)] >> (p & 31)) & 1u;
        int n = g_sidx[cls * NBOX + p];
        g_keep[n * NC + cls] = (unsigned char)kept;
    }
}

// ---------------- 7: masked argmax -> obj_preds ----------------
__global__ void k_argmax(float* __restrict__ out) {
    int n = blockIdx.x * 256 + threadIdx.x;
    if (n >= NBOX) return;
    float best = -1.f;
    int bestc = 0;
    for (int c = 1; c < NCLS; c++) {
        float v = g_keep[n * NC + (c - 1)] ? g_probs[n * NCLS + c] : 0.f;
        if (v > best) { best = v; bestc = c; }
    }
    out[OUT_PREDS + n] = (float)bestc;
}

// ---------------- launch ----------------
extern "C" void kernel_launch(void* const* d_in, const int* in_sizes, int n_in,
                              void* d_out, int out_size) {
    const float*  logits = (const float*)d_in[0];
    const float*  vr     = (const float*)d_in[1];
    const float4* boxes  = (const float4*)d_in[2];
    const float*  W      = (const float*)d_in[3];
    const float*  b      = (const float*)d_in[4];
    float* out = (float*)d_out;

    static cudaStream_t s2 = nullptr;
    static cudaEvent_t  evA = nullptr, evB = nullptr;
    if (!s2) {
        cudaStreamCreateWithFlags(&s2, cudaStreamNonBlocking);
        cudaEventCreateWithFlags(&evA, cudaEventDisableTiming);
        cudaEventCreateWithFlags(&evB, cudaEventDisableTiming);
    }

    const int scan_smem = (NBOX * 32 + 32) * 4;          // 131200
    const int gemm_smem = 256 * 33 * 4 + 32 * 26 * 8;    // 40448
    cudaFuncSetAttribute(k_scan, cudaFuncAttributeMaxDynamicSharedMemorySize, scan_smem);
    cudaFuncSetAttribute(k_gemm, cudaFuncAttributeMaxDynamicSharedMemorySize, gemm_smem);

    // fork point: GEMM branch depends on nothing upstream
    cudaEventRecord(evA, 0);
    cudaStreamWaitEvent(s2, evA, 0);

    k_softmax<<<128, 256>>>(logits, out);                          // slot 1
    k_sort<<<NC, 512>>>(boxes);                                    // slot 2
    k_initrel<<<(MROW * NREL + 255) / 256, 256, 0, s2>>>(b, out);  // slot 3
    k_iou<<<dim3((NTASK + 31) / 32, NC), 1024>>>();                // slot 4 (profiled)
    k_gemm<<<dim3(16, 16), 256, gemm_smem, s2>>>(vr, W, out);      // slot 5
    k_scan<<<NC, 512, scan_smem>>>();                              // slot 6
    k_argmax<<<4, 256>>>(out);                                     // slot 7

    cudaEventRecord(evB, s2);
    cudaStreamWaitEvent(0, evB, 0);
}